// round 2
// baseline (speedup 1.0000x reference)
#include <cuda_runtime.h>
#include <cuda_bf16.h>
#include <stdint.h>

// out[b, :] = (1/K) * sum_k table[idx[b,k], :]
// table: [V, 128] fp32 -> 32 float4/row, one per lane. One warp per output row.
// Index dtype (int32 vs int64) detected at runtime by a tiny prologue kernel.

#define DIM 128
#define V4_PER_ROW (DIM / 4)   // 32

__device__ int g_idx_is64;

__global__ void detect_idx_dtype_kernel(const unsigned int* __restrict__ raw)
{
    // int64 little-endian with values < 2^31: every odd 32-bit word is 0.
    // Random int32 indices in [0, 200000): probability all-zero ~ 0.
    int is64 = 1;
    #pragma unroll
    for (int i = 0; i < 32; i++) {
        if (raw[2 * i + 1] != 0u) { is64 = 0; break; }
    }
    g_idx_is64 = is64;
}

template <typename IdxT>
__device__ __forceinline__ float4 gather_row(const float4* __restrict__ table,
                                             const IdxT* __restrict__ ip,
                                             int K, int lane)
{
    float4 acc = make_float4(0.f, 0.f, 0.f, 0.f);
    int k = 0;
    for (; k + 4 <= K; k += 4) {
        const long long n0 = (long long)__ldg(ip + k + 0);
        const long long n1 = (long long)__ldg(ip + k + 1);
        const long long n2 = (long long)__ldg(ip + k + 2);
        const long long n3 = (long long)__ldg(ip + k + 3);

        const float4 v0 = __ldg(table + n0 * V4_PER_ROW + lane);
        const float4 v1 = __ldg(table + n1 * V4_PER_ROW + lane);
        const float4 v2 = __ldg(table + n2 * V4_PER_ROW + lane);
        const float4 v3 = __ldg(table + n3 * V4_PER_ROW + lane);

        acc.x += v0.x + v1.x + v2.x + v3.x;
        acc.y += v0.y + v1.y + v2.y + v3.y;
        acc.z += v0.z + v1.z + v2.z + v3.z;
        acc.w += v0.w + v1.w + v2.w + v3.w;
    }
    for (; k < K; k++) {
        const long long n = (long long)__ldg(ip + k);
        const float4 v = __ldg(table + n * V4_PER_ROW + lane);
        acc.x += v.x; acc.y += v.y; acc.z += v.z; acc.w += v.w;
    }
    return acc;
}

__global__ __launch_bounds__(256, 8)
void gather_mean_kernel(const float4* __restrict__ table,
                        const void* __restrict__ idx,
                        float4* __restrict__ out,
                        int B, int K, float inv_k)
{
    const int warps_per_block = blockDim.x >> 5;
    const int row  = blockIdx.x * warps_per_block + (threadIdx.x >> 5);
    const int lane = threadIdx.x & 31;
    if (row >= B) return;

    float4 acc;
    if (g_idx_is64) {
        const long long* __restrict__ ip = (const long long*)idx + (long long)row * K;
        acc = gather_row<long long>(table, ip, K, lane);
    } else {
        const int* __restrict__ ip = (const int*)idx + (long long)row * K;
        acc = gather_row<int>(table, ip, K, lane);
    }

    acc.x *= inv_k; acc.y *= inv_k; acc.z *= inv_k; acc.w *= inv_k;
    out[(long long)row * V4_PER_ROW + lane] = acc;
}

extern "C" void kernel_launch(void* const* d_in, const int* in_sizes, int n_in,
                              void* d_out, int out_size)
{
    const float4* table = (const float4*)d_in[0];   // [V, 128] fp32
    const void*   idx   = d_in[1];                  // [B, K] int32 or int64
    float4*       out   = (float4*)d_out;           // [B, 128] fp32

    const int B = out_size / DIM;        // 50000
    const int K = in_sizes[1] / B;       // 32 (element count is dtype-independent)

    detect_idx_dtype_kernel<<<1, 1>>>((const unsigned int*)idx);

    const int threads = 256;             // 8 warps -> 8 rows/block
    const int rows_per_block = threads / 32;
    const int grid = (B + rows_per_block - 1) / rows_per_block;

    gather_mean_kernel<<<grid, threads>>>(table, idx, out, B, K, 1.0f / (float)K);
}

// round 5
// speedup vs baseline: 1.0919x; 1.0919x over previous
#include <cuda_runtime.h>
#include <cuda_bf16.h>
#include <stdint.h>

// out[b, :] = (1/K) * sum_k table[idx[b,k], :]
// table: [V, 128] fp32 -> 32 float4/row, one per lane. One warp per output row.
// L2 policy: table gathers = evict_last via createpolicy + L2::cache_hint,
//            index reads   = streaming (__ldcs),
//            output writes = streaming (__stcs).
// K-loop unrolled x8 for MLP.

#define DIM 128
#define V4_PER_ROW (DIM / 4)   // 32

__device__ int g_idx_is64;

__global__ void detect_idx_dtype_kernel(const unsigned int* __restrict__ raw)
{
    // int64 little-endian with values < 2^31: every odd 32-bit word is 0.
    int is64 = 1;
    #pragma unroll
    for (int i = 0; i < 32; i++) {
        if (raw[2 * i + 1] != 0u) { is64 = 0; break; }
    }
    g_idx_is64 = is64;
}

// 128-bit gather with L2 evict-last policy (keeps table lines resident).
__device__ __forceinline__ float4 ldg_el(const float4* __restrict__ p,
                                         unsigned long long policy)
{
    float4 v;
    asm volatile("ld.global.nc.L2::cache_hint.v4.f32 {%0,%1,%2,%3}, [%4], %5;"
                 : "=f"(v.x), "=f"(v.y), "=f"(v.z), "=f"(v.w)
                 : "l"(p), "l"(policy));
    return v;
}

template <typename IdxT>
__device__ __forceinline__ float4 gather_row(const float4* __restrict__ table,
                                             const IdxT* __restrict__ ip,
                                             int K, int lane,
                                             unsigned long long policy)
{
    float4 acc = make_float4(0.f, 0.f, 0.f, 0.f);
    int k = 0;
    for (; k + 8 <= K; k += 8) {
        long long n[8];
        #pragma unroll
        for (int j = 0; j < 8; j++) n[j] = (long long)__ldcs(ip + k + j);

        float4 v[8];
        #pragma unroll
        for (int j = 0; j < 8; j++)
            v[j] = ldg_el(table + n[j] * V4_PER_ROW + lane, policy);

        #pragma unroll
        for (int j = 0; j < 8; j++) {
            acc.x += v[j].x; acc.y += v[j].y; acc.z += v[j].z; acc.w += v[j].w;
        }
    }
    for (; k < K; k++) {
        const long long n = (long long)__ldcs(ip + k);
        const float4 v = ldg_el(table + n * V4_PER_ROW + lane, policy);
        acc.x += v.x; acc.y += v.y; acc.z += v.z; acc.w += v.w;
    }
    return acc;
}

__global__ __launch_bounds__(256, 8)
void gather_mean_kernel(const float4* __restrict__ table,
                        const void* __restrict__ idx,
                        float4* __restrict__ out,
                        int B, int K, float inv_k)
{
    const int warps_per_block = blockDim.x >> 5;
    const int row  = blockIdx.x * warps_per_block + (threadIdx.x >> 5);
    const int lane = threadIdx.x & 31;
    if (row >= B) return;

    // evict_last policy for the embedding-table lines
    unsigned long long policy;
    asm volatile("createpolicy.fractional.L2::evict_last.b64 %0, 1.0;"
                 : "=l"(policy));

    float4 acc;
    if (g_idx_is64) {
        const long long* __restrict__ ip = (const long long*)idx + (long long)row * K;
        acc = gather_row<long long>(table, ip, K, lane, policy);
    } else {
        const int* __restrict__ ip = (const int*)idx + (long long)row * K;
        acc = gather_row<int>(table, ip, K, lane, policy);
    }

    acc.x *= inv_k; acc.y *= inv_k; acc.z *= inv_k; acc.w *= inv_k;
    __stcs(&out[(long long)row * V4_PER_ROW + lane], acc);  // streaming store
}

extern "C" void kernel_launch(void* const* d_in, const int* in_sizes, int n_in,
                              void* d_out, int out_size)
{
    const float4* table = (const float4*)d_in[0];   // [V, 128] fp32
    const void*   idx   = d_in[1];                  // [B, K] int32 or int64
    float4*       out   = (float4*)d_out;           // [B, 128] fp32

    const int B = out_size / DIM;        // 50000
    const int K = in_sizes[1] / B;       // 32

    detect_idx_dtype_kernel<<<1, 1>>>((const unsigned int*)idx);

    const int threads = 256;             // 8 warps -> 8 rows/block
    const int rows_per_block = threads / 32;
    const int grid = (B + rows_per_block - 1) / rows_per_block;

    gather_mean_kernel<<<grid, threads>>>(table, idx, out, B, K, 1.0f / (float)K);
}

// round 9
// speedup vs baseline: 1.0961x; 1.0039x over previous
#include <cuda_runtime.h>
#include <cuda_bf16.h>
#include <stdint.h>

// out[b, :] = (1/K) * sum_k table[idx[b,k], :]
// table: [V, 128] fp32 -> 32 float4/row, one per lane. One warp per output row.
// L2 policy: table gathers = evict_last via createpolicy + L2::cache_hint,
//            index reads   = streaming (__ldcs),
//            output writes = streaming (__stcs).
// K-loop unrolled x8; launch_bounds(256,4) gives ptxas a 64-reg budget so all
// 8 LDG.E.128 stay in flight (R5 post-mortem: regs=32 had serialized the unroll).

#define DIM 128
#define V4_PER_ROW (DIM / 4)   // 32

__device__ int g_idx_is64;

__global__ void detect_idx_dtype_kernel(const unsigned int* __restrict__ raw)
{
    // int64 little-endian with values < 2^31: every odd 32-bit word is 0.
    int is64 = 1;
    #pragma unroll
    for (int i = 0; i < 32; i++) {
        if (raw[2 * i + 1] != 0u) { is64 = 0; break; }
    }
    g_idx_is64 = is64;
}

// 128-bit gather with L2 evict-last policy (keeps table lines resident).
__device__ __forceinline__ float4 ldg_el(const float4* __restrict__ p,
                                         unsigned long long policy)
{
    float4 v;
    asm volatile("ld.global.nc.L2::cache_hint.v4.f32 {%0,%1,%2,%3}, [%4], %5;"
                 : "=f"(v.x), "=f"(v.y), "=f"(v.z), "=f"(v.w)
                 : "l"(p), "l"(policy));
    return v;
}

template <typename IdxT>
__device__ __forceinline__ float4 gather_row(const float4* __restrict__ table,
                                             const IdxT* __restrict__ ip,
                                             int K, int lane,
                                             unsigned long long policy)
{
    float4 acc = make_float4(0.f, 0.f, 0.f, 0.f);
    int k = 0;
    for (; k + 8 <= K; k += 8) {
        const float4* p[8];
        #pragma unroll
        for (int j = 0; j < 8; j++)
            p[j] = table + (long long)__ldcs(ip + k + j) * V4_PER_ROW + lane;

        float4 v[8];
        #pragma unroll
        for (int j = 0; j < 8; j++) v[j] = ldg_el(p[j], policy);

        #pragma unroll
        for (int j = 0; j < 8; j++) {
            acc.x += v[j].x; acc.y += v[j].y; acc.z += v[j].z; acc.w += v[j].w;
        }
    }
    for (; k < K; k++) {
        const long long n = (long long)__ldcs(ip + k);
        const float4 v = ldg_el(table + n * V4_PER_ROW + lane, policy);
        acc.x += v.x; acc.y += v.y; acc.z += v.z; acc.w += v.w;
    }
    return acc;
}

__global__ __launch_bounds__(256, 4)
void gather_mean_kernel(const float4* __restrict__ table,
                        const void* __restrict__ idx,
                        float4* __restrict__ out,
                        int B, int K, float inv_k)
{
    const int warps_per_block = blockDim.x >> 5;
    const int row  = blockIdx.x * warps_per_block + (threadIdx.x >> 5);
    const int lane = threadIdx.x & 31;
    if (row >= B) return;

    // evict_last policy for the embedding-table lines
    unsigned long long policy;
    asm volatile("createpolicy.fractional.L2::evict_last.b64 %0, 1.0;"
                 : "=l"(policy));

    float4 acc;
    if (g_idx_is64) {
        const long long* __restrict__ ip = (const long long*)idx + (long long)row * K;
        acc = gather_row<long long>(table, ip, K, lane, policy);
    } else {
        const int* __restrict__ ip = (const int*)idx + (long long)row * K;
        acc = gather_row<int>(table, ip, K, lane, policy);
    }

    acc.x *= inv_k; acc.y *= inv_k; acc.z *= inv_k; acc.w *= inv_k;
    __stcs(&out[(long long)row * V4_PER_ROW + lane], acc);  // streaming store
}

extern "C" void kernel_launch(void* const* d_in, const int* in_sizes, int n_in,
                              void* d_out, int out_size)
{
    const float4* table = (const float4*)d_in[0];   // [V, 128] fp32
    const void*   idx   = d_in[1];                  // [B, K] int32 or int64
    float4*       out   = (float4*)d_out;           // [B, 128] fp32

    const int B = out_size / DIM;        // 50000
    const int K = in_sizes[1] / B;       // 32

    detect_idx_dtype_kernel<<<1, 1>>>((const unsigned int*)idx);

    const int threads = 256;             // 8 warps -> 8 rows/block
    const int rows_per_block = threads / 32;
    const int grid = (B + rows_per_block - 1) / rows_per_block;

    gather_mean_kernel<<<grid, threads>>>(table, idx, out, B, K, 1.0f / (float)K);
}